// round 17
// baseline (speedup 1.0000x reference)
#include <cuda_runtime.h>
#include <cuda_fp16.h>
#include <math.h>
#include <stdint.h>

// Flash attention w/ bias + causal, fp32 I/O, fp16 mma.sync (m16n8k16).
// 2 CTAs/SM, 54KB smem. Affine 144B-stride smem, exp2 softmax computed in
// packed f16x2 (result doubles as the PV A-fragment), FFMA bias fold,
// STS.128 staging, warp-vote rescale skip, masked-group skipping.

#define SEQ 1024
#define BM  128
#define BKT 64
#define RS  144                  // smem row stride bytes (128 data + 16 pad)

#define SM_QH  0u
#define SM_KV  18432u
#define KVSZ   18432u
#define KV_K   0u
#define KV_V   9216u
#define SM_TOTAL 55296

#define SCALE_L2E 0.18033688011112042f   // 0.125 * log2(e)
#define LOG2E     1.4426950408889634f

static __device__ __forceinline__ uint32_t smem_u32(const void* p) {
    uint32_t a;
    asm("{ .reg .u64 t; cvta.to.shared.u64 t, %1; cvt.u32.u64 %0, t; }" : "=r"(a) : "l"(p));
    return a;
}
static __device__ __forceinline__ float ex2(float x) {
    float r; asm("ex2.approx.f32 %0, %1;" : "=f"(r) : "f"(x));
    return r;
}
static __device__ __forceinline__ uint32_t h2ex2(uint32_t x) {
    uint32_t r; asm("ex2.approx.f16x2 %0, %1;" : "=r"(r) : "r"(x));
    return r;
}
static __device__ __forceinline__ uint32_t hpair(float a, float b) {
    __half2 t = __floats2half2_rn(a, b);
    return *reinterpret_cast<uint32_t*>(&t);
}
static __device__ __forceinline__ float2 h2f2(uint32_t p) {
    __half2 t = *reinterpret_cast<__half2*>(&p);
    return __half22float2(t);
}
static __device__ __forceinline__ void ldsm4(uint32_t r[4], uint32_t addr) {
    asm volatile("ldmatrix.sync.aligned.m8n8.x4.shared.b16 {%0,%1,%2,%3}, [%4];"
                 : "=r"(r[0]), "=r"(r[1]), "=r"(r[2]), "=r"(r[3]) : "r"(addr));
}
static __device__ __forceinline__ void ldsm4t(uint32_t r[4], uint32_t addr) {
    asm volatile("ldmatrix.sync.aligned.m8n8.x4.trans.shared.b16 {%0,%1,%2,%3}, [%4];"
                 : "=r"(r[0]), "=r"(r[1]), "=r"(r[2]), "=r"(r[3]) : "r"(addr));
}
static __device__ __forceinline__ void mmaf16(float c[4], const uint32_t a[4], uint32_t b0, uint32_t b1) {
    asm volatile("mma.sync.aligned.m16n8k16.row.col.f32.f16.f16.f32 "
                 "{%0,%1,%2,%3}, {%4,%5,%6,%7}, {%8,%9}, {%0,%1,%2,%3};"
                 : "+f"(c[0]), "+f"(c[1]), "+f"(c[2]), "+f"(c[3])
                 : "r"(a[0]), "r"(a[1]), "r"(a[2]), "r"(a[3]), "r"(b0), "r"(b1));
}

__global__ __launch_bounds__(256, 2)
void attn_f16_kernel(const float* __restrict__ q,
                     const float* __restrict__ k,
                     const float* __restrict__ v,
                     const float* __restrict__ bias,
                     float* __restrict__ out)
{
    extern __shared__ char smem[];
    const uint32_t sb = smem_u32(smem);
    const int tid  = threadIdx.x;
    const int wid  = tid >> 5;
    const int lane = tid & 31;
    const int qd   = lane & 3;
    const int sel  = lane >> 3;

    const int m  = 7 - (int)(blockIdx.x >> 6);   // heavy CTAs first
    const int bh = (int)(blockIdx.x & 63);

    // ---- prologue: stage Q (scaled by 0.125*log2e, single fp16) ----
    const float* qp = q + ((size_t)bh * SEQ + (size_t)m * BM) * 64;
    #pragma unroll
    for (int i = 0; i < 8; ++i) {
        int lin = tid + i * 256;
        int row = lin >> 4;
        int d4  = (lin & 15) * 4;
        float4 v4 = *reinterpret_cast<const float4*>(qp + row * 64 + d4);
        uint32_t off = (uint32_t)(row * RS + (lin & 15) * 8);
        *reinterpret_cast<uint2*>(smem + SM_QH + off) =
            make_uint2(hpair(v4.x * SCALE_L2E, v4.y * SCALE_L2E),
                       hpair(v4.z * SCALE_L2E, v4.w * SCALE_L2E));
    }

    const int wr0 = wid * 16;
    const int gra = m * BM + wr0 + (lane >> 2);
    const int grb = gra + 8;

    // loop-invariant fragment base addresses
    const uint32_t aoff = (uint32_t)((wr0 + (lane & 7) + ((sel & 1) << 3)) * RS + (sel >> 1) * 16);
    const uint32_t qhb  = sb + SM_QH + aoff;
    const uint32_t boff = (uint32_t)((((sel >> 1) << 3) + (lane & 7)) * RS + (sel & 1) * 16);
    const uint32_t voff = (uint32_t)((((sel & 1) << 3) + (lane & 7)) * RS + (sel >> 1) * 16);

    // staging coords: 2 chunks of 16B-fp16 (=32B fp32) each for K and V
    const int crow0 = tid >> 3,           cch0 = tid & 7;
    const int crow1 = (tid + 256) >> 3,   cch1 = tid & 7;   // +256 keeps ch, row += 32

    float s[8][4];
    float o[8][4];
    #pragma unroll
    for (int nb = 0; nb < 8; ++nb)
        #pragma unroll
        for (int e = 0; e < 4; ++e) o[nb][e] = 0.f;
    float m_a = -INFINITY, m_b = -INFINITY, l_a = 0.f, l_b = 0.f;

    const int ntiles = 2 * m + 2;
    const int wlast  = m * BM + wr0 + 15;

    for (int n = 0; n < ntiles; ++n) {
        // ---- stage K and V (single fp16, STS.128) into buffer n&1 ----
        const uint32_t kvb = SM_KV + (uint32_t)(n & 1) * KVSZ;
        const float* kp = k + ((size_t)bh * SEQ + (size_t)n * BKT) * 64;
        const float* vp = v + ((size_t)bh * SEQ + (size_t)n * BKT) * 64;
        {
            const int rows[2] = {crow0, crow1};
            const int chs[2]  = {cch0, cch1};
            #pragma unroll
            for (int j = 0; j < 2; ++j) {
                const float* ksrc = kp + rows[j] * 64 + chs[j] * 8;
                float4 a4 = *reinterpret_cast<const float4*>(ksrc);
                float4 b4 = *reinterpret_cast<const float4*>(ksrc + 4);
                uint32_t off = (uint32_t)(rows[j] * RS + chs[j] * 16);
                *reinterpret_cast<uint4*>(smem + kvb + KV_K + off) =
                    make_uint4(hpair(a4.x, a4.y), hpair(a4.z, a4.w),
                               hpair(b4.x, b4.y), hpair(b4.z, b4.w));
                const float* vsrc = vp + rows[j] * 64 + chs[j] * 8;
                float4 c4 = *reinterpret_cast<const float4*>(vsrc);
                float4 d4 = *reinterpret_cast<const float4*>(vsrc + 4);
                *reinterpret_cast<uint4*>(smem + kvb + KV_V + off) =
                    make_uint4(hpair(c4.x, c4.y), hpair(c4.z, c4.w),
                               hpair(d4.x, d4.y), hpair(d4.z, d4.w));
            }
        }
        __syncthreads();   // single barrier per tile

        const bool active = (n * BKT <= wlast);
        if (active) {
            const uint32_t KB = sb + kvb + KV_K + boff;
            const uint32_t VB = sb + kvb + KV_V + voff;
            const bool fullvis = (n * BKT + BKT - 1 <= m * BM + wr0);

            bool vis[4];
            #pragma unroll
            for (int g = 0; g < 4; ++g)
                vis[g] = fullvis || (n * BKT + g * 16 <= wlast);

            // bias prefetch (raw; LOG2E folded via FFMA below)
            float2 ba[8], bb[8];
            {
                const float* bpa = bias + ((size_t)bh * SEQ + gra) * SEQ + (size_t)n * BKT;
                const float* bpb = bias + ((size_t)bh * SEQ + grb) * SEQ + (size_t)n * BKT;
                #pragma unroll
                for (int nb = 0; nb < 8; ++nb) {
                    ba[nb] = *reinterpret_cast<const float2*>(bpa + nb * 8 + 2 * qd);
                    bb[nb] = *reinterpret_cast<const float2*>(bpb + nb * 8 + 2 * qd);
                }
            }

            // ---- S = Q*K (single pass, skip fully-masked groups) ----
            #pragma unroll
            for (int nb = 0; nb < 8; ++nb)
                #pragma unroll
                for (int e = 0; e < 4; ++e) s[nb][e] = 0.f;
            #pragma unroll
            for (int kk = 0; kk < 4; ++kk) {
                uint32_t aq[4];
                ldsm4(aq, qhb + (uint32_t)(kk * 32));
                #pragma unroll
                for (int nb2 = 0; nb2 < 4; ++nb2) {
                    if (vis[nb2]) {
                        uint32_t bk[4];
                        ldsm4(bk, KB + (uint32_t)(nb2 * 16 * RS + kk * 32));
                        mmaf16(s[2 * nb2],     aq, bk[0], bk[1]);
                        mmaf16(s[2 * nb2 + 1], aq, bk[2], bk[3]);
                    }
                }
            }

            // ---- bias FFMA fold (+ causal mask only on diagonal tiles) ----
            if (fullvis) {
                #pragma unroll
                for (int nb = 0; nb < 8; ++nb) {
                    s[nb][0] = fmaf(ba[nb].x, LOG2E, s[nb][0]);
                    s[nb][1] = fmaf(ba[nb].y, LOG2E, s[nb][1]);
                    s[nb][2] = fmaf(bb[nb].x, LOG2E, s[nb][2]);
                    s[nb][3] = fmaf(bb[nb].y, LOG2E, s[nb][3]);
                }
            } else {
                const int c00 = n * BKT + 2 * qd;
                #pragma unroll
                for (int nb = 0; nb < 8; ++nb) {
                    int c0 = c00 + nb * 8, c1 = c0 + 1;
                    s[nb][0] = (c0 <= gra) ? fmaf(ba[nb].x, LOG2E, s[nb][0]) : -INFINITY;
                    s[nb][1] = (c1 <= gra) ? fmaf(ba[nb].y, LOG2E, s[nb][1]) : -INFINITY;
                    s[nb][2] = (c0 <= grb) ? fmaf(bb[nb].x, LOG2E, s[nb][2]) : -INFINITY;
                    s[nb][3] = (c1 <= grb) ? fmaf(bb[nb].y, LOG2E, s[nb][3]) : -INFINITY;
                }
            }

            // ---- online softmax (log2 domain, packed f16x2 exp) ----
            float tma = -INFINITY, tmb = -INFINITY;
            #pragma unroll
            for (int nb = 0; nb < 8; ++nb) {
                tma = fmaxf(tma, fmaxf(s[nb][0], s[nb][1]));
                tmb = fmaxf(tmb, fmaxf(s[nb][2], s[nb][3]));
            }
            tma = fmaxf(tma, __shfl_xor_sync(0xffffffffu, tma, 1));
            tma = fmaxf(tma, __shfl_xor_sync(0xffffffffu, tma, 2));
            tmb = fmaxf(tmb, __shfl_xor_sync(0xffffffffu, tmb, 1));
            tmb = fmaxf(tmb, __shfl_xor_sync(0xffffffffu, tmb, 2));

            float mna = fmaxf(m_a, tma), mnb = fmaxf(m_b, tmb);
            float ca = ex2(m_a - mna), cb = ex2(m_b - mnb);
            m_a = mna; m_b = mnb;

            uint32_t ph[8][2];   // packed fp16 P: [nb][0]=rowsA pair, [nb][1]=rowsB pair
            float pa = 0.f, pb = 0.f;
            #pragma unroll
            for (int nb = 0; nb < 8; ++nb) {
                uint32_t p01 = h2ex2(hpair(s[nb][0] - mna, s[nb][1] - mna));
                uint32_t p23 = h2ex2(hpair(s[nb][2] - mnb, s[nb][3] - mnb));
                ph[nb][0] = p01; ph[nb][1] = p23;
                float2 f01 = h2f2(p01);
                float2 f23 = h2f2(p23);
                pa += f01.x + f01.y;
                pb += f23.x + f23.y;
            }
            pa += __shfl_xor_sync(0xffffffffu, pa, 1);
            pa += __shfl_xor_sync(0xffffffffu, pa, 2);
            pb += __shfl_xor_sync(0xffffffffu, pb, 1);
            pb += __shfl_xor_sync(0xffffffffu, pb, 2);
            l_a = l_a * ca + pa;
            l_b = l_b * cb + pb;

            // skip O rescale when the max didn't move anywhere in the warp
            if (!__all_sync(0xffffffffu, (ca == 1.f) && (cb == 1.f))) {
                #pragma unroll
                for (int nb = 0; nb < 8; ++nb) {
                    o[nb][0] *= ca; o[nb][1] *= ca;
                    o[nb][2] *= cb; o[nb][3] *= cb;
                }
            }

            // ---- O += P*V (P already packed as A-fragments) ----
            #pragma unroll
            for (int kk = 0; kk < 4; ++kk) {
                if (vis[kk]) {
                    uint32_t ap[4] = { ph[2 * kk][0], ph[2 * kk][1],
                                       ph[2 * kk + 1][0], ph[2 * kk + 1][1] };
                    #pragma unroll
                    for (int nb2 = 0; nb2 < 4; ++nb2) {
                        uint32_t bv[4];
                        ldsm4t(bv, VB + (uint32_t)(kk * 16 * RS + nb2 * 32));
                        mmaf16(o[2 * nb2],     ap, bv[0], bv[1]);
                        mmaf16(o[2 * nb2 + 1], ap, bv[2], bv[3]);
                    }
                }
            }
        }
    }

    // ---- epilogue ----
    const float ia = 1.f / l_a, ib = 1.f / l_b;
    float* opa = out + ((size_t)bh * SEQ + gra) * 64;
    float* opb = out + ((size_t)bh * SEQ + grb) * 64;
    #pragma unroll
    for (int nb = 0; nb < 8; ++nb) {
        int col = nb * 8 + 2 * qd;
        *reinterpret_cast<float2*>(opa + col) = make_float2(o[nb][0] * ia, o[nb][1] * ia);
        *reinterpret_cast<float2*>(opb + col) = make_float2(o[nb][2] * ib, o[nb][3] * ib);
    }
}

extern "C" void kernel_launch(void* const* d_in, const int* in_sizes, int n_in,
                              void* d_out, int out_size)
{
    const float* q    = (const float*)d_in[0];
    const float* k    = (const float*)d_in[1];
    const float* v    = (const float*)d_in[2];
    const float* bias = (const float*)d_in[3];
    float* out = (float*)d_out;

    cudaFuncSetAttribute(attn_f16_kernel,
                         cudaFuncAttributeMaxDynamicSharedMemorySize, SM_TOTAL);
    attn_f16_kernel<<<512, 256, SM_TOTAL>>>(q, k, v, bias, out);
}